// round 2
// baseline (speedup 1.0000x reference)
#include <cuda_runtime.h>
#include <math.h>

#define MAXN 131072

__device__ float g_h[MAXN];     // x @ W            [N]
__device__ float g_deg[MAXN];   // degree (float)   [N]
__device__ float g_dinv[MAXN];  // rsqrt(deg)       [N]
__device__ float g_p[MAXN];     // dinv * h         [N]
__device__ float g_acc[MAXN];   // scatter target   [N]

// ---------------------------------------------------------------------------
// K1: h[n] = dot(x[n,:], W[:,0]); init deg=1 (self loop), acc=0.
// One warp per row, float4 loads, 256 cols -> 2 float4 per lane.
// ---------------------------------------------------------------------------
__global__ void k1_linear_init(const float* __restrict__ x,
                               const float* __restrict__ W,
                               int N, int C) {
    int warp = (blockIdx.x * blockDim.x + threadIdx.x) >> 5;
    int lane = threadIdx.x & 31;
    if (warp >= N) return;

    const float4* xr = reinterpret_cast<const float4*>(x + (size_t)warp * C);
    const float4* w4 = reinterpret_cast<const float4*>(W);

    // C = 256 -> 64 float4 per row -> 2 per lane
    float4 a0 = xr[lane];
    float4 a1 = xr[lane + 32];
    float4 b0 = __ldg(&w4[lane]);
    float4 b1 = __ldg(&w4[lane + 32]);

    float s = a0.x * b0.x + a0.y * b0.y + a0.z * b0.z + a0.w * b0.w
            + a1.x * b1.x + a1.y * b1.y + a1.z * b1.z + a1.w * b1.w;

    #pragma unroll
    for (int off = 16; off > 0; off >>= 1)
        s += __shfl_xor_sync(0xffffffffu, s, off);

    if (lane == 0) {
        g_h[warp]   = s;
        g_deg[warp] = 1.0f;   // self loop
        g_acc[warp] = 0.0f;
    }
}

// ---------------------------------------------------------------------------
// K2: degree count over dst (edge_index delivered as int32 by harness)
// ---------------------------------------------------------------------------
__global__ void k2_degree(const int* __restrict__ dst, int E) {
    int i = blockIdx.x * blockDim.x + threadIdx.x;
    int stride = gridDim.x * blockDim.x;
    for (; i < E; i += stride) {
        atomicAdd(&g_deg[dst[i]], 1.0f);
    }
}

// ---------------------------------------------------------------------------
// K3: dinv = rsqrt(deg); p = dinv * h
// ---------------------------------------------------------------------------
__global__ void k3_norm(int N) {
    int i = blockIdx.x * blockDim.x + threadIdx.x;
    if (i < N) {
        float dinv = rsqrtf(g_deg[i]);   // deg >= 1 always (self loop)
        g_dinv[i] = dinv;
        g_p[i] = dinv * g_h[i];
    }
}

// ---------------------------------------------------------------------------
// K4: scatter messages: acc[dst] += p[src]
// ---------------------------------------------------------------------------
__global__ void k4_scatter(const int* __restrict__ src,
                           const int* __restrict__ dst, int E) {
    int i = blockIdx.x * blockDim.x + threadIdx.x;
    int stride = gridDim.x * blockDim.x;
    for (; i < E; i += stride) {
        int s = src[i];
        int d = dst[i];
        atomicAdd(&g_acc[d], g_p[s]);
    }
}

// ---------------------------------------------------------------------------
// K5: out = softplus(dinv * (acc + p) + b)
// (self-loop term: dinv*dinv*h = dinv*p)
// ---------------------------------------------------------------------------
__global__ void k5_epilogue(float* __restrict__ out,
                            const float* __restrict__ b, int N) {
    int i = blockIdx.x * blockDim.x + threadIdx.x;
    if (i < N) {
        float v = g_dinv[i] * (g_acc[i] + g_p[i]) + b[0];
        // numerically stable softplus
        out[i] = fmaxf(v, 0.0f) + log1pf(expf(-fabsf(v)));
    }
}

extern "C" void kernel_launch(void* const* d_in, const int* in_sizes, int n_in,
                              void* d_out, int out_size) {
    const float* x   = (const float*)d_in[0];
    const int*   ei  = (const int*)d_in[1];   // [2, E], int32 (harness downcasts int64)
    const float* W   = (const float*)d_in[2];
    const float* b   = (const float*)d_in[3];
    float*       out = (float*)d_out;

    int C = in_sizes[2];            // 256
    int N = in_sizes[0] / C;        // 100000
    int E = in_sizes[1] / 2;        // 3200000

    const int* src = ei;
    const int* dst = ei + E;

    // K1: one warp per row; 256 threads = 8 warps/block
    {
        int warps_per_block = 8;
        int blocks = (N + warps_per_block - 1) / warps_per_block;
        k1_linear_init<<<blocks, 256>>>(x, W, N, C);
    }
    // K2: degree
    {
        int threads = 256;
        int blocks = (E + threads - 1) / threads;
        if (blocks > 65535) blocks = 65535;
        k2_degree<<<blocks, threads>>>(dst, E);
    }
    // K3: norm
    {
        int threads = 256;
        int blocks = (N + threads - 1) / threads;
        k3_norm<<<blocks, threads>>>(N);
    }
    // K4: message scatter
    {
        int threads = 256;
        int blocks = (E + threads - 1) / threads;
        if (blocks > 65535) blocks = 65535;
        k4_scatter<<<blocks, threads>>>(src, dst, E);
    }
    // K5: epilogue
    {
        int threads = 256;
        int blocks = (N + threads - 1) / threads;
        k5_epilogue<<<blocks, threads>>>(out, b, N);
    }
}

// round 4
// speedup vs baseline: 1.0657x; 1.0657x over previous
#include <cuda_runtime.h>
#include <stdint.h>
#include <math.h>

#define MAXN 131072

__device__ float g_h[MAXN];     // x @ W                 [N]
__device__ float g_deg[MAXN];   // edge-degree (no self) [N]
__device__ float g_dinv[MAXN];  // rsqrt(deg+1)          [N]
__device__ float g_p[MAXN];     // dinv * h              [N]
__device__ float g_acc[MAXN];   // scatter target        [N]

// ---------------------------------------------------------------------------
// K0: zero the degree accumulator (must precede fused kernel's atomics)
// ---------------------------------------------------------------------------
__global__ void k0_zero_deg(int N) {
    int i = blockIdx.x * blockDim.x + threadIdx.x;
    if (i < N) g_deg[i] = 0.0f;
}

// ---------------------------------------------------------------------------
// K1 (fused): per-warp row dot products (DRAM-bound) + grid-stride degree
// histogram (L2-atomic-bound). Independent work, disjoint pipes -> overlap.
// ---------------------------------------------------------------------------
__global__ void k1_fused(const float* __restrict__ x,
                         const float* __restrict__ W,
                         const int*   __restrict__ dst,
                         int N, int C, int E) {
    int tid  = blockIdx.x * blockDim.x + threadIdx.x;
    int warp = tid >> 5;
    int lane = tid & 31;

    // Part A: h[row] = dot(x[row,:], W), acc[row] = 0
    if (warp < N) {
        const float4* xr = reinterpret_cast<const float4*>(x + (size_t)warp * C);
        const float4* w4 = reinterpret_cast<const float4*>(W);

        float4 a0 = xr[lane];
        float4 a1 = xr[lane + 32];
        float4 b0 = __ldg(&w4[lane]);
        float4 b1 = __ldg(&w4[lane + 32]);

        float s = a0.x * b0.x + a0.y * b0.y + a0.z * b0.z + a0.w * b0.w
                + a1.x * b1.x + a1.y * b1.y + a1.z * b1.z + a1.w * b1.w;

        #pragma unroll
        for (int off = 16; off > 0; off >>= 1)
            s += __shfl_xor_sync(0xffffffffu, s, off);

        if (lane == 0) {
            g_h[warp]   = s;
            g_acc[warp] = 0.0f;
        }
    }

    // Part B: degree histogram over dst (overlaps with Part A's DRAM traffic)
    int stride = gridDim.x * blockDim.x;
    for (int i = tid; i < E; i += stride)
        atomicAdd(&g_deg[dst[i]], 1.0f);
}

// ---------------------------------------------------------------------------
// K3: dinv = rsqrt(deg + 1 (self loop)); p = dinv * h
// ---------------------------------------------------------------------------
__global__ void k3_norm(int N) {
    int i = blockIdx.x * blockDim.x + threadIdx.x;
    if (i < N) {
        float dinv = rsqrtf(g_deg[i] + 1.0f);
        g_dinv[i] = dinv;
        g_p[i] = dinv * g_h[i];
    }
}

// ---------------------------------------------------------------------------
// K4: scatter messages acc[dst] += p[src], 4 edges/thread (int4 index loads)
// for memory-level parallelism on the L2 gather+atomic path.
// ---------------------------------------------------------------------------
__global__ void k4_scatter_vec(const int* __restrict__ src,
                               const int* __restrict__ dst,
                               int E4, int E) {
    int i = blockIdx.x * blockDim.x + threadIdx.x;
    if (i < E4) {
        int4 s4 = reinterpret_cast<const int4*>(src)[i];
        int4 d4 = reinterpret_cast<const int4*>(dst)[i];
        float p0 = g_p[s4.x];
        float p1 = g_p[s4.y];
        float p2 = g_p[s4.z];
        float p3 = g_p[s4.w];
        atomicAdd(&g_acc[d4.x], p0);
        atomicAdd(&g_acc[d4.y], p1);
        atomicAdd(&g_acc[d4.z], p2);
        atomicAdd(&g_acc[d4.w], p3);
    }
    // scalar tail (E % 4 edges)
    int base = E4 * 4;
    int t = base + i;
    if (i < E - base)
        atomicAdd(&g_acc[dst[t]], g_p[src[t]]);
}

// scalar fallback if dst pointer can't be read as int4
__global__ void k4_scatter_scalar(const int* __restrict__ src,
                                  const int* __restrict__ dst, int E) {
    int i = blockIdx.x * blockDim.x + threadIdx.x;
    int stride = gridDim.x * blockDim.x;
    for (; i < E; i += stride)
        atomicAdd(&g_acc[dst[i]], g_p[src[i]]);
}

// ---------------------------------------------------------------------------
// K5: out = softplus(dinv * (acc + p) + b)   (self-loop term dinv^2 h = dinv*p)
// ---------------------------------------------------------------------------
__global__ void k5_epilogue(float* __restrict__ out,
                            const float* __restrict__ b, int N) {
    int i = blockIdx.x * blockDim.x + threadIdx.x;
    if (i < N) {
        float v = g_dinv[i] * (g_acc[i] + g_p[i]) + b[0];
        out[i] = fmaxf(v, 0.0f) + log1pf(expf(-fabsf(v)));
    }
}

extern "C" void kernel_launch(void* const* d_in, const int* in_sizes, int n_in,
                              void* d_out, int out_size) {
    const float* x   = (const float*)d_in[0];
    const int*   ei  = (const int*)d_in[1];   // [2, E], int32
    const float* W   = (const float*)d_in[2];
    const float* b   = (const float*)d_in[3];
    float*       out = (float*)d_out;

    int C = in_sizes[2];            // 256
    int N = in_sizes[0] / C;        // 100000
    int E = in_sizes[1] / 2;        // 3200000

    const int* src = ei;
    const int* dst = ei + E;

    // K0: zero degree
    {
        int threads = 256;
        int blocks = (N + threads - 1) / threads;
        k0_zero_deg<<<blocks, threads>>>(N);
    }
    // K1 fused: rows need ceil(N/8) blocks of 256 (8 warps); edges grid-stride
    {
        int warps_per_block = 8;
        int blocks = (N + warps_per_block - 1) / warps_per_block;
        k1_fused<<<blocks, 256>>>(x, W, dst, N, C, E);
    }
    // K3
    {
        int threads = 256;
        int blocks = (N + threads - 1) / threads;
        k3_norm<<<blocks, threads>>>(N);
    }
    // K4: vectorized if dst is 16B-aligned (ei 16B-aligned and E % 4 == 0)
    {
        int threads = 256;
        bool aligned = ((E % 4) == 0) &&
                       ((((unsigned long long)(size_t)ei) & 15ull) == 0ull);
        if (aligned) {
            int E4 = E / 4;
            int blocks = (E4 + threads - 1) / threads;
            k4_scatter_vec<<<blocks, threads>>>(src, dst, E4, E);
        } else {
            int blocks = (E + threads - 1) / threads;
            if (blocks > 65535) blocks = 65535;
            k4_scatter_scalar<<<blocks, threads>>>(src, dst, E);
        }
    }
    // K5
    {
        int threads = 256;
        int blocks = (N + threads - 1) / threads;
        k5_epilogue<<<blocks, threads>>>(out, b, N);
    }
}

// round 5
// speedup vs baseline: 1.1219x; 1.0527x over previous
#include <cuda_runtime.h>
#include <stdint.h>
#include <math.h>

#define MAXN 131072
#define PAD  8   // one float per 32B L2 sector for atomic targets

__device__ float g_h[MAXN];            // x @ W                    [N]
__device__ float g_dinv[MAXN];         // rsqrt(deg+1)             [N]
__device__ float g_p[MAXN];            // dinv * h                 [N]
__device__ float g_deg8[MAXN * PAD];   // sector-padded degree     [N*8], zeroed after use
__device__ float g_acc8[MAXN * PAD];   // sector-padded scatter    [N*8], zeroed after use

// ---------------------------------------------------------------------------
// K1 (fused): per-warp row dot products (DRAM-bound) + grid-stride degree
// histogram into sector-padded bins (L2-atomic). Disjoint pipes -> overlap.
// g_deg8 is guaranteed zero on entry (static zero-init on first call,
// re-zeroed by k3 on every call).
// ---------------------------------------------------------------------------
__global__ void k1_fused(const float* __restrict__ x,
                         const float* __restrict__ W,
                         const int*   __restrict__ dst,
                         int N, int C, int E) {
    int tid  = blockIdx.x * blockDim.x + threadIdx.x;
    int warp = tid >> 5;
    int lane = tid & 31;

    // Part A: h[row] = dot(x[row,:], W)
    if (warp < N) {
        const float4* xr = reinterpret_cast<const float4*>(x + (size_t)warp * C);
        const float4* w4 = reinterpret_cast<const float4*>(W);

        float4 a0 = xr[lane];
        float4 a1 = xr[lane + 32];
        float4 b0 = __ldg(&w4[lane]);
        float4 b1 = __ldg(&w4[lane + 32]);

        float s = a0.x * b0.x + a0.y * b0.y + a0.z * b0.z + a0.w * b0.w
                + a1.x * b1.x + a1.y * b1.y + a1.z * b1.z + a1.w * b1.w;

        #pragma unroll
        for (int off = 16; off > 0; off >>= 1)
            s += __shfl_xor_sync(0xffffffffu, s, off);

        if (lane == 0) g_h[warp] = s;
    }

    // Part B: degree histogram (sector-padded targets)
    int stride = gridDim.x * blockDim.x;
    for (int i = tid; i < E; i += stride)
        atomicAdd(&g_deg8[(unsigned)dst[i] * PAD], 1.0f);
}

// ---------------------------------------------------------------------------
// K3: dinv = rsqrt(deg+1); p = dinv*h; re-zero deg bin for the next replay.
// ---------------------------------------------------------------------------
__global__ void k3_norm(int N) {
    int i = blockIdx.x * blockDim.x + threadIdx.x;
    if (i < N) {
        float d = g_deg8[(unsigned)i * PAD];
        g_deg8[(unsigned)i * PAD] = 0.0f;
        float dinv = rsqrtf(d + 1.0f);
        g_dinv[i] = dinv;
        g_p[i] = dinv * g_h[i];
    }
}

// ---------------------------------------------------------------------------
// K4: scatter acc[dst] += p[src] into sector-padded bins. Scalar grid-stride
// (best measured shape); gathers of dense g_p keep L1 hit rate.
// ---------------------------------------------------------------------------
__global__ void k4_scatter(const int* __restrict__ src,
                           const int* __restrict__ dst, int E) {
    int i = blockIdx.x * blockDim.x + threadIdx.x;
    int stride = gridDim.x * blockDim.x;
    for (; i < E; i += stride) {
        int s = src[i];
        int d = dst[i];
        atomicAdd(&g_acc8[(unsigned)d * PAD], g_p[s]);
    }
}

// ---------------------------------------------------------------------------
// K5: out = softplus(dinv*(acc+p) + b); re-zero acc bin for the next replay.
// (self-loop term dinv^2 h = dinv*p)
// ---------------------------------------------------------------------------
__global__ void k5_epilogue(float* __restrict__ out,
                            const float* __restrict__ b, int N) {
    int i = blockIdx.x * blockDim.x + threadIdx.x;
    if (i < N) {
        float a = g_acc8[(unsigned)i * PAD];
        g_acc8[(unsigned)i * PAD] = 0.0f;
        float v = g_dinv[i] * (a + g_p[i]) + b[0];
        out[i] = fmaxf(v, 0.0f) + log1pf(expf(-fabsf(v)));
    }
}

extern "C" void kernel_launch(void* const* d_in, const int* in_sizes, int n_in,
                              void* d_out, int out_size) {
    const float* x   = (const float*)d_in[0];
    const int*   ei  = (const int*)d_in[1];   // [2, E], int32
    const float* W   = (const float*)d_in[2];
    const float* b   = (const float*)d_in[3];
    float*       out = (float*)d_out;

    int C = in_sizes[2];            // 256
    int N = in_sizes[0] / C;        // 100000
    int E = in_sizes[1] / 2;        // 3200000

    const int* src = ei;
    const int* dst = ei + E;

    // K1 fused: ceil(N/8) blocks of 256 (8 warps = 8 rows/block); edges grid-stride
    {
        int warps_per_block = 8;
        int blocks = (N + warps_per_block - 1) / warps_per_block;
        k1_fused<<<blocks, 256>>>(x, W, dst, N, C, E);
    }
    // K3
    {
        int threads = 256;
        int blocks = (N + threads - 1) / threads;
        k3_norm<<<blocks, threads>>>(N);
    }
    // K4: scalar grid-stride
    {
        int threads = 256;
        int blocks = (E + threads - 1) / threads;
        if (blocks > 65535) blocks = 65535;
        k4_scatter<<<blocks, threads>>>(src, dst, E);
    }
    // K5
    {
        int threads = 256;
        int blocks = (N + threads - 1) / threads;
        k5_epilogue<<<blocks, threads>>>(out, b, N);
    }
}

// round 6
// speedup vs baseline: 1.1934x; 1.0638x over previous
#include <cuda_runtime.h>
#include <stdint.h>
#include <math.h>

#define MAXN 131072
#define PAD  8   // one float per 32B L2 sector for atomic targets

__device__ float g_h[MAXN];            // x @ W                    [N]
__device__ float g_dinv[MAXN];         // rsqrt(deg+1)             [N]
__device__ float g_p[MAXN];            // dinv * h                 [N]
__device__ float g_deg8[MAXN * PAD];   // sector-padded degree     (zeroed after use)
__device__ float g_acc8[MAXN * PAD];   // sector-padded scatter    (zeroed after use)

// ---------------------------------------------------------------------------
// K1 (fused): per-warp row dot products (DRAM-bound) + grid-stride degree
// histogram into sector-padded bins (LTS-atomic). Disjoint pipes -> overlap.
// g_deg8 is zero on entry (static zero-init; re-zeroed by k3 every call).
// ---------------------------------------------------------------------------
__global__ void k1_fused(const float* __restrict__ x,
                         const float* __restrict__ W,
                         const int*   __restrict__ dst,
                         int N, int C, int E) {
    int tid  = blockIdx.x * blockDim.x + threadIdx.x;
    int warp = tid >> 5;
    int lane = tid & 31;

    // Part A: h[row] = dot(x[row,:], W)
    if (warp < N) {
        const float4* xr = reinterpret_cast<const float4*>(x + (size_t)warp * C);
        const float4* w4 = reinterpret_cast<const float4*>(W);

        float4 a0 = xr[lane];
        float4 a1 = xr[lane + 32];
        float4 b0 = __ldg(&w4[lane]);
        float4 b1 = __ldg(&w4[lane + 32]);

        float s = a0.x * b0.x + a0.y * b0.y + a0.z * b0.z + a0.w * b0.w
                + a1.x * b1.x + a1.y * b1.y + a1.z * b1.z + a1.w * b1.w;

        #pragma unroll
        for (int off = 16; off > 0; off >>= 1)
            s += __shfl_xor_sync(0xffffffffu, s, off);

        if (lane == 0) g_h[warp] = s;
    }

    // Part B: degree histogram (sector-padded targets)
    int stride = gridDim.x * blockDim.x;
    for (int i = tid; i < E; i += stride)
        atomicAdd(&g_deg8[(unsigned)dst[i] * PAD], 1.0f);
}

// ---------------------------------------------------------------------------
// K3: dinv = rsqrt(deg+1); p = dinv*h; re-zero deg bin. 2 nodes/thread (ILP).
// ---------------------------------------------------------------------------
__global__ void k3_norm(int N) {
    int t = blockIdx.x * blockDim.x + threadIdx.x;
    int i0 = t * 2;
    int i1 = i0 + 1;
    if (i0 < N) {
        float d0 = g_deg8[(unsigned)i0 * PAD];
        float d1 = (i1 < N) ? g_deg8[(unsigned)i1 * PAD] : 0.0f;
        float h0 = g_h[i0];
        float h1 = (i1 < N) ? g_h[i1] : 0.0f;

        g_deg8[(unsigned)i0 * PAD] = 0.0f;
        float v0 = rsqrtf(d0 + 1.0f);
        g_dinv[i0] = v0;
        g_p[i0] = v0 * h0;

        if (i1 < N) {
            g_deg8[(unsigned)i1 * PAD] = 0.0f;
            float v1 = rsqrtf(d1 + 1.0f);
            g_dinv[i1] = v1;
            g_p[i1] = v1 * h1;
        }
    }
}

// ---------------------------------------------------------------------------
// K4: scatter acc[dst] += p[src] into sector-padded bins. Scalar grid-stride
// (measured-best shape); at the LTS sector-traffic floor.
// ---------------------------------------------------------------------------
__global__ void k4_scatter(const int* __restrict__ src,
                           const int* __restrict__ dst, int E) {
    int i = blockIdx.x * blockDim.x + threadIdx.x;
    int stride = gridDim.x * blockDim.x;
    for (; i < E; i += stride) {
        int s = src[i];
        int d = dst[i];
        atomicAdd(&g_acc8[(unsigned)d * PAD], g_p[s]);
    }
}

// ---------------------------------------------------------------------------
// K5: out = softplus(dinv*(acc+p) + b); re-zero acc bin. 2 nodes/thread.
// (self-loop term dinv^2 h = dinv*p)
// ---------------------------------------------------------------------------
__global__ void k5_epilogue(float* __restrict__ out,
                            const float* __restrict__ b, int N) {
    int t = blockIdx.x * blockDim.x + threadIdx.x;
    int i0 = t * 2;
    int i1 = i0 + 1;
    if (i0 < N) {
        float bb = b[0];
        float a0 = g_acc8[(unsigned)i0 * PAD];
        float a1 = (i1 < N) ? g_acc8[(unsigned)i1 * PAD] : 0.0f;
        float p0 = g_p[i0];
        float p1 = (i1 < N) ? g_p[i1] : 0.0f;
        float q0 = g_dinv[i0];
        float q1 = (i1 < N) ? g_dinv[i1] : 0.0f;

        g_acc8[(unsigned)i0 * PAD] = 0.0f;
        float v0 = q0 * (a0 + p0) + bb;
        out[i0] = fmaxf(v0, 0.0f) + log1pf(expf(-fabsf(v0)));

        if (i1 < N) {
            g_acc8[(unsigned)i1 * PAD] = 0.0f;
            float v1 = q1 * (a1 + p1) + bb;
            out[i1] = fmaxf(v1, 0.0f) + log1pf(expf(-fabsf(v1)));
        }
    }
}

extern "C" void kernel_launch(void* const* d_in, const int* in_sizes, int n_in,
                              void* d_out, int out_size) {
    const float* x   = (const float*)d_in[0];
    const int*   ei  = (const int*)d_in[1];   // [2, E], int32
    const float* W   = (const float*)d_in[2];
    const float* b   = (const float*)d_in[3];
    float*       out = (float*)d_out;

    int C = in_sizes[2];            // 256
    int N = in_sizes[0] / C;        // 100000
    int E = in_sizes[1] / 2;        // 3200000

    const int* src = ei;
    const int* dst = ei + E;

    // K1 fused: 512 threads = 16 warps = 16 rows/block; edges grid-stride
    {
        int warps_per_block = 16;
        int blocks = (N + warps_per_block - 1) / warps_per_block;
        k1_fused<<<blocks, 512>>>(x, W, dst, N, C, E);
    }
    // K3: 2 nodes/thread
    {
        int threads = 256;
        int work = (N + 1) / 2;
        int blocks = (work + threads - 1) / threads;
        k3_norm<<<blocks, threads>>>(N);
    }
    // K4: scalar grid-stride
    {
        int threads = 256;
        int blocks = (E + threads - 1) / threads;
        if (blocks > 65535) blocks = 65535;
        k4_scatter<<<blocks, threads>>>(src, dst, E);
    }
    // K5: 2 nodes/thread
    {
        int threads = 256;
        int work = (N + 1) / 2;
        int blocks = (work + threads - 1) / threads;
        k5_epilogue<<<blocks, threads>>>(out, b, N);
    }
}